// round 5
// baseline (speedup 1.0000x reference)
#include <cuda_runtime.h>
#include <cstdint>

#define HIDDEN 128
#define FEAT   512
#define MAX_NODES 12000

// Scratch: aggregated raw features per destination node.
__device__ float g_agg[(size_t)MAX_NODES * FEAT];
__device__ int g_idx64;

// ---------------------------------------------------------------------------
// Phase 0: zero aggregation scratch
// ---------------------------------------------------------------------------
__global__ void zero_kernel(int n4) {
    int i = blockIdx.x * blockDim.x + threadIdx.x;
    if (i < n4) reinterpret_cast<float4*>(g_agg)[i] = make_float4(0.f, 0.f, 0.f, 0.f);
}

// Phase 0b: detect edge_index dtype (int64 vs int32) from data
__global__ void detect_kernel(const long long* __restrict__ ei, long long n) {
    __shared__ int ok;
    if (threadIdx.x == 0) ok = 1;
    __syncthreads();
    long long v = ei[threadIdx.x];
    if (v < 0 || v >= n) ok = 0;
    __syncthreads();
    if (threadIdx.x == 0) g_idx64 = ok;
}

// ---------------------------------------------------------------------------
// Phase 1: edge scatter (1 warp/edge, vector atomics into L2-resident scratch)
// ---------------------------------------------------------------------------
__global__ void scatter_kernel(const float* __restrict__ x,
                               const void* __restrict__ ei, int E) {
    int gw   = (blockIdx.x * blockDim.x + threadIdx.x) >> 5;
    int lane = threadIdx.x & 31;
    if (gw >= E) return;

    long long row, col;
    if (g_idx64) {
        const long long* e64 = (const long long*)ei;
        row = e64[gw];
        col = e64[(size_t)E + gw];
    } else {
        const int* e32 = (const int*)ei;
        row = e32[gw];
        col = e32[(size_t)E + gw];
    }

    const float4* src = (const float4*)(x + (size_t)col * FEAT);
    float*        dst = g_agg + (size_t)row * FEAT;

#pragma unroll
    for (int i = 0; i < 4; ++i) {
        float4 v = src[lane + 32 * i];
        float* p = dst + (size_t)(lane + 32 * i) * 4;
        asm volatile("red.global.add.v4.f32 [%0], {%1, %2, %3, %4};"
                     :: "l"(p), "f"(v.x), "f"(v.y), "f"(v.z), "f"(v.w)
                     : "memory");
    }
}

// ---------------------------------------------------------------------------
// Phase 2: tf32 mma.sync GEMM with cp.async double-buffered pipeline.
// Per CTA: 128 nodes x 128 out-cols.  1D grid, heavy (vector) blocks first.
//   scalar slice: out = scalar@Wsroot.T + agg_s@Wsrel.T + bias  (K=256)
//   vector slice: out = vector@Wvroot.T + agg_v@Wvrel.T         (K=768)
// 256 threads = 8 warps (4x2); warp tile 32x64 = 2x8 m16n8k8 subtiles.
// Raw fp32 staged in smem (stride 36 -> conflict-free), cvt at fragment load.
// ---------------------------------------------------------------------------
#define SAS 36            // smem row stride (floats)
#define TILEF (128 * SAS) // floats per tile buffer

#define MMA_TF32(c, a, b)                                                   \
    asm volatile("mma.sync.aligned.m16n8k8.row.col.f32.tf32.tf32.f32 "      \
                 "{%0,%1,%2,%3}, {%4,%5,%6,%7}, {%8,%9}, {%0,%1,%2,%3};"    \
                 : "+f"((c)[0]), "+f"((c)[1]), "+f"((c)[2]), "+f"((c)[3])   \
                 : "r"((a)[0]), "r"((a)[1]), "r"((a)[2]), "r"((a)[3]),      \
                   "r"((b)[0]), "r"((b)[1]))

#define CP16(dst, src, sz)                                                  \
    asm volatile("cp.async.cg.shared.global [%0], [%1], 16, %2;"            \
                 :: "r"(dst), "l"(src), "r"(sz) : "memory")
#define CP_COMMIT() asm volatile("cp.async.commit_group;" ::: "memory")

__device__ __forceinline__ uint32_t f2tf32(float v) {
    uint32_t r;
    asm("cvt.rna.tf32.f32 %0, %1;" : "=r"(r) : "f"(v));
    return r;
}
__device__ __forceinline__ uint32_t smem_u32(const void* p) {
    uint32_t a;
    asm("{ .reg .u64 t; cvta.to.shared.u64 t, %1; cvt.u32.u64 %0, t; }"
        : "=r"(a) : "l"(p));
    return a;
}

__global__ __launch_bounds__(256, 2)
void mma_gemm_kernel(const float* __restrict__ x,
                     const float* __restrict__ Wsrel,
                     const float* __restrict__ Wsroot,
                     const float* __restrict__ bias,
                     const float* __restrict__ Wvrel,
                     const float* __restrict__ Wvroot,
                     float* __restrict__ out, int n, int nvec) {
    extern __shared__ float dsm[];
    __shared__ float sbias[128];

    const int tid  = threadIdx.x;
    const int wid  = tid >> 5;
    const int lane = tid & 31;
    const int gid  = lane >> 2;      // 0..7
    const int tig  = lane & 3;       // 0..3
    const int wm   = wid >> 1;       // 0..3 (m-warp)
    const int wn   = wid & 1;        // 0..1 (n-warp)

    // 1D grid decode: heavy vector blocks first, then scalar blocks
    const int bx = blockIdx.x;
    int by, mx;
    if (bx < 3 * nvec) { by = 1 + bx % 3; mx = bx / 3; }
    else               { by = 0;          mx = bx - 3 * nvec; }
    const int m0 = mx * 128;

    int Khalf, ldb, aoff;
    const float* B0;
    const float* B1;
    if (by == 0) {
        Khalf = 128; ldb = 128; aoff = 0;
        B0 = Wsroot; B1 = Wsrel;
    } else {
        Khalf = 384; ldb = 384; aoff = 128;
        B0 = Wvroot + (size_t)(by - 1) * 128 * 384;
        B1 = Wvrel  + (size_t)(by - 1) * 128 * 384;
    }
    const int C  = (2 * Khalf) / 32;   // 8 or 24 K-chunks
    const int Ch = C / 2;

    if (tid < 128) sbias[tid] = (by == 0) ? bias[tid] : 0.f;

    float* Asb[2] = { dsm,             dsm + TILEF };
    float* Bsb[2] = { dsm + 2 * TILEF, dsm + 3 * TILEF };

    // loader mapping: 2 threads per 32-float row, 4x 16B chunks each
    const int lrow  = tid >> 1;
    const int lcol0 = (tid & 1) * 16;
    const uint32_t sAd[2] = { smem_u32(&Asb[0][lrow * SAS + lcol0]),
                              smem_u32(&Asb[1][lrow * SAS + lcol0]) };
    const uint32_t sBd[2] = { smem_u32(&Bsb[0][lrow * SAS + lcol0]),
                              smem_u32(&Bsb[1][lrow * SAS + lcol0]) };
    const int anode = m0 + lrow;

    // issue loads for chunk `it` into stage `st`
    auto load_tile = [&](int st, int it) {
        const int pass = (it >= Ch);
        const int kt   = (it - pass * Ch) * 32;
        const float* Ab = (pass ? (const float*)g_agg : x) + aoff;
        const uint32_t asz = (pass || anode < n) ? 16u : 0u;
        const float* asrc = Ab + (size_t)anode * FEAT + kt + lcol0;
        const float* Bb = pass ? B1 : B0;
        const float* bsrc = Bb + (size_t)lrow * ldb + kt + lcol0;
#pragma unroll
        for (int i = 0; i < 4; ++i)
            CP16(sAd[st] + 16 * i, asrc + 4 * i, asz);
#pragma unroll
        for (int i = 0; i < 4; ++i)
            CP16(sBd[st] + 16 * i, bsrc + 4 * i, 16u);
        CP_COMMIT();
    };

    float acc[2][8][4];
#pragma unroll
    for (int mt = 0; mt < 2; ++mt)
#pragma unroll
        for (int nt = 0; nt < 8; ++nt)
#pragma unroll
            for (int j = 0; j < 4; ++j) acc[mt][nt][j] = 0.f;

    // prologue: stage 0 and 1 in flight
    load_tile(0, 0);
    load_tile(1, 1);

#pragma unroll 1
    for (int it = 0; it < C; ++it) {
        const int st = it & 1;
        if (it < C - 1)
            asm volatile("cp.async.wait_group 1;" ::: "memory");
        else
            asm volatile("cp.async.wait_group 0;" ::: "memory");
        __syncthreads();

        const float* As = Asb[st];
        const float* Bs = Bsb[st];
#pragma unroll
        for (int k8 = 0; k8 < 4; ++k8) {
            const int kc = k8 * 8 + tig;
            uint32_t a[2][4], b[8][2];
#pragma unroll
            for (int mt = 0; mt < 2; ++mt) {
                const int r = wm * 32 + mt * 16 + gid;
                a[mt][0] = f2tf32(As[r * SAS + kc]);
                a[mt][1] = f2tf32(As[(r + 8) * SAS + kc]);
                a[mt][2] = f2tf32(As[r * SAS + kc + 4]);
                a[mt][3] = f2tf32(As[(r + 8) * SAS + kc + 4]);
            }
#pragma unroll
            for (int nt = 0; nt < 8; ++nt) {
                const int cidx = wn * 64 + nt * 8 + gid;
                b[nt][0] = f2tf32(Bs[cidx * SAS + kc]);
                b[nt][1] = f2tf32(Bs[cidx * SAS + kc + 4]);
            }
#pragma unroll
            for (int mt = 0; mt < 2; ++mt)
#pragma unroll
                for (int nt = 0; nt < 8; ++nt)
                    MMA_TF32(acc[mt][nt], a[mt], b[nt]);
        }

        if (it + 2 < C) {
            __syncthreads();           // all warps done reading stage st
            load_tile(st, it + 2);
        }
    }

    // ---- epilogue ----
#pragma unroll
    for (int mt = 0; mt < 2; ++mt) {
        const int r0 = m0 + wm * 32 + mt * 16 + gid;
#pragma unroll
        for (int nt = 0; nt < 8; ++nt) {
            const int cl = wn * 64 + nt * 8 + 2 * tig;
            const float b0 = sbias[cl], b1 = sbias[cl + 1];
            if (r0 < n) {
                float2 v = make_float2(acc[mt][nt][0] + b0, acc[mt][nt][1] + b1);
                *(float2*)(out + (size_t)r0 * FEAT + by * 128 + cl) = v;
            }
            if (r0 + 8 < n) {
                float2 v = make_float2(acc[mt][nt][2] + b0, acc[mt][nt][3] + b1);
                *(float2*)(out + (size_t)(r0 + 8) * FEAT + by * 128 + cl) = v;
            }
        }
    }
}

// ---------------------------------------------------------------------------
extern "C" void kernel_launch(void* const* d_in, const int* in_sizes, int n_in,
                              void* d_out, int out_size) {
    const float* x      = (const float*)d_in[0];
    const void*  ei     = d_in[1];
    const float* Wsrel  = (const float*)d_in[2];
    const float* Wsroot = (const float*)d_in[3];
    const float* bs     = (const float*)d_in[4];
    const float* Wvrel  = (const float*)d_in[5];
    const float* Wvroot = (const float*)d_in[6];
    float*       out    = (float*)d_out;

    const int n = in_sizes[0] / FEAT;        // 10000
    const int E = in_sizes[1] / 2;           // 160000

    // Phase 0
    const int n4 = n * FEAT / 4;
    zero_kernel<<<(n4 + 255) / 256, 256>>>(n4);
    detect_kernel<<<1, 64>>>((const long long*)ei, (long long)n);

    // Phase 1
    const int blocks = (E * 32 + 255) / 256;
    scatter_kernel<<<blocks, 256>>>(x, ei, E);

    // Phase 2 (tf32 mma.sync, cp.async pipelined)
    const int nvec  = (n + 127) / 128;       // 79 M-tiles
    const int DSMEM = 4 * TILEF * 4;         // 73728 B
    static int smem_set = 0;
    if (!smem_set) {
        cudaFuncSetAttribute(mma_gemm_kernel,
                             cudaFuncAttributeMaxDynamicSharedMemorySize, DSMEM);
        smem_set = 1;
    }
    mma_gemm_kernel<<<4 * nvec, 256, DSMEM>>>(x, Wsrel, Wsroot, bs,
                                              Wvrel, Wvroot, out, n, nvec);
}